// round 3
// baseline (speedup 1.0000x reference)
#include <cuda_runtime.h>
#include <cuda_bf16.h>
#include <math.h>

// Problem constants
#define B_   4
#define HW_  4096          // 64*64
#define C_   512
#define G_   32
#define CG_  16            // channels per group
#define MTOT (B_*HW_)      // 16384

// ---------------- scratch (device globals; no allocations allowed) ----------
__device__ float g_xn[(size_t)MTOT * C_];
__device__ float g_q [(size_t)MTOT * C_];
__device__ float g_k [(size_t)MTOT * C_];
__device__ float g_v [(size_t)MTOT * C_];
__device__ float g_s [(size_t)B_ * HW_ * HW_];   // 256 MiB scores
__device__ float g_ao[(size_t)MTOT * C_];

// ---------------- GroupNorm ------------------------------------------------
// one block per (batch, group); 256 threads
__global__ __launch_bounds__(256) void groupnorm_kernel(
    const float* __restrict__ x, const float* __restrict__ gamma,
    const float* __restrict__ beta, float* __restrict__ xn)
{
    int bg = blockIdx.x;
    int b = bg / G_, g = bg % G_;
    const float* xp = x + (size_t)b * HW_ * C_ + g * CG_;
    float* op = xn + (size_t)b * HW_ * C_ + g * CG_;
    int tid = threadIdx.x;

    float s = 0.f, ss = 0.f;
    for (int p = tid; p < HW_; p += 256) {
        const float4* v4 = (const float4*)(xp + (size_t)p * C_);
        #pragma unroll
        for (int i = 0; i < 4; i++) {
            float4 t = v4[i];
            s  += t.x + t.y + t.z + t.w;
            ss += t.x*t.x + t.y*t.y + t.z*t.z + t.w*t.w;
        }
    }
    __shared__ float rs[256], rq[256];
    rs[tid] = s; rq[tid] = ss; __syncthreads();
    for (int o = 128; o > 0; o >>= 1) {
        if (tid < o) { rs[tid] += rs[tid+o]; rq[tid] += rq[tid+o]; }
        __syncthreads();
    }
    const float invn = 1.0f / (HW_ * CG_);
    float mean = rs[0] * invn;
    float var  = rq[0] * invn - mean * mean;
    float rstd = rsqrtf(var + 1e-6f);

    // per-channel affine params for this group
    float gm[CG_], bt[CG_];
    #pragma unroll
    for (int i = 0; i < CG_; i++) {
        gm[i] = gamma[g*CG_ + i];
        bt[i] = beta [g*CG_ + i];
    }

    for (int p = tid; p < HW_; p += 256) {
        const float4* v4 = (const float4*)(xp + (size_t)p * C_);
        float4* o4 = (float4*)(op + (size_t)p * C_);
        #pragma unroll
        for (int i = 0; i < 4; i++) {
            float4 t = v4[i];
            float4 r;
            r.x = (t.x - mean) * rstd * gm[i*4+0] + bt[i*4+0];
            r.y = (t.y - mean) * rstd * gm[i*4+1] + bt[i*4+1];
            r.z = (t.z - mean) * rstd * gm[i*4+2] + bt[i*4+2];
            r.w = (t.w - mean) * rstd * gm[i*4+3] + bt[i*4+3];
            o4[i] = r;
        }
    }
}

// ---------------- SGEMM 128x128x8, 8x8 micro-tile, 256 threads ---------------
// C = alpha * A*op(B) (+bias)(+resid). A: MxK row-major. B: KxN (transB=0) or
// NxK (transB=1), row-major. C: MxN row-major. blockIdx.z batches via strides.
// M,N multiples of 128; K multiple of 8 (true for all our shapes).
__global__ __launch_bounds__(256) void sgemm_kernel(
    const float* __restrict__ A, const float* __restrict__ B,
    float* __restrict__ C,
    int M, int N, int K,
    long long sAb, long long sBb, long long sCb,
    int transB, float alpha,
    const float* __restrict__ bias,
    const float* __restrict__ resid)
{
    A += (long long)blockIdx.z * sAb;
    B += (long long)blockIdx.z * sBb;
    C += (long long)blockIdx.z * sCb;

    __shared__ float As[8][128];
    __shared__ float Bs[8][128];

    const int tid = threadIdx.x;
    const int brow = blockIdx.y * 128;
    const int bcol = blockIdx.x * 128;

    // A-tile load mapping: 128 rows x 8 k, 2 float4 per row -> 1 float4/thread
    const int a_row = tid >> 1;
    const int a_col = (tid & 1) * 4;
    // B-tile NN load mapping: 8 k-rows x 128 cols -> 1 float4/thread
    const int b_row = tid >> 5;
    const int b_col = (tid & 31) * 4;

    const int tr = tid >> 4;   // 0..15
    const int tc = tid & 15;   // 0..15

    float acc[8][8];
    #pragma unroll
    for (int i = 0; i < 8; i++)
        #pragma unroll
        for (int j = 0; j < 8; j++) acc[i][j] = 0.f;

    for (int k0 = 0; k0 < K; k0 += 8) {
        float4 av = *(const float4*)(A + (long long)(brow + a_row) * K + k0 + a_col);
        As[a_col+0][a_row] = av.x;
        As[a_col+1][a_row] = av.y;
        As[a_col+2][a_row] = av.z;
        As[a_col+3][a_row] = av.w;
        if (!transB) {
            float4 bv = *(const float4*)(B + (long long)(k0 + b_row) * N + bcol + b_col);
            *(float4*)&Bs[b_row][b_col] = bv;
        } else {
            float4 bv = *(const float4*)(B + (long long)(bcol + a_row) * K + k0 + a_col);
            Bs[a_col+0][a_row] = bv.x;
            Bs[a_col+1][a_row] = bv.y;
            Bs[a_col+2][a_row] = bv.z;
            Bs[a_col+3][a_row] = bv.w;
        }
        __syncthreads();

        #pragma unroll
        for (int k = 0; k < 8; k++) {
            float4 a0 = *(const float4*)&As[k][tr*8];
            float4 a1 = *(const float4*)&As[k][tr*8+4];
            float4 b0 = *(const float4*)&Bs[k][tc*8];
            float4 b1 = *(const float4*)&Bs[k][tc*8+4];
            float ar[8] = {a0.x,a0.y,a0.z,a0.w,a1.x,a1.y,a1.z,a1.w};
            float br[8] = {b0.x,b0.y,b0.z,b0.w,b1.x,b1.y,b1.z,b1.w};
            #pragma unroll
            for (int i = 0; i < 8; i++)
                #pragma unroll
                for (int j = 0; j < 8; j++)
                    acc[i][j] = fmaf(ar[i], br[j], acc[i][j]);
        }
        __syncthreads();
    }

    // epilogue
    float bia[8];
    if (bias) {
        float4 c0 = *(const float4*)(bias + bcol + tc*8);
        float4 c1 = *(const float4*)(bias + bcol + tc*8 + 4);
        bia[0]=c0.x; bia[1]=c0.y; bia[2]=c0.z; bia[3]=c0.w;
        bia[4]=c1.x; bia[5]=c1.y; bia[6]=c1.z; bia[7]=c1.w;
    }
    #pragma unroll
    for (int i = 0; i < 8; i++) {
        long long row = brow + tr*8 + i;
        long long base = row * N + bcol + tc*8;
        float v[8];
        #pragma unroll
        for (int j = 0; j < 8; j++) v[j] = acc[i][j] * alpha;
        if (bias) {
            #pragma unroll
            for (int j = 0; j < 8; j++) v[j] += bia[j];
        }
        if (resid) {
            float4 r0 = *(const float4*)(resid + base);
            float4 r1 = *(const float4*)(resid + base + 4);
            v[0]+=r0.x; v[1]+=r0.y; v[2]+=r0.z; v[3]+=r0.w;
            v[4]+=r1.x; v[5]+=r1.y; v[6]+=r1.z; v[7]+=r1.w;
        }
        float4 o0 = {v[0],v[1],v[2],v[3]};
        float4 o1 = {v[4],v[5],v[6],v[7]};
        *(float4*)(C + base)     = o0;
        *(float4*)(C + base + 4) = o1;
    }
}

// ---------------- row softmax (4096 per row, in-place) -----------------------
__global__ __launch_bounds__(256) void softmax_kernel(float* __restrict__ S)
{
    __shared__ float red[256];
    float* p = S + (long long)blockIdx.x * HW_;
    int tid = threadIdx.x;

    float4 v[4];
    float mx = -1e30f;
    #pragma unroll
    for (int i = 0; i < 4; i++) {
        v[i] = ((const float4*)p)[tid + i*256];
        mx = fmaxf(mx, fmaxf(fmaxf(v[i].x, v[i].y), fmaxf(v[i].z, v[i].w)));
    }
    red[tid] = mx; __syncthreads();
    for (int o = 128; o > 0; o >>= 1) {
        if (tid < o) red[tid] = fmaxf(red[tid], red[tid+o]);
        __syncthreads();
    }
    mx = red[0]; __syncthreads();

    float sum = 0.f;
    #pragma unroll
    for (int i = 0; i < 4; i++) {
        v[i].x = __expf(v[i].x - mx);
        v[i].y = __expf(v[i].y - mx);
        v[i].z = __expf(v[i].z - mx);
        v[i].w = __expf(v[i].w - mx);
        sum += v[i].x + v[i].y + v[i].z + v[i].w;
    }
    red[tid] = sum; __syncthreads();
    for (int o = 128; o > 0; o >>= 1) {
        if (tid < o) red[tid] += red[tid+o];
        __syncthreads();
    }
    float inv = 1.0f / red[0];
    #pragma unroll
    for (int i = 0; i < 4; i++) {
        v[i].x *= inv; v[i].y *= inv; v[i].z *= inv; v[i].w *= inv;
        ((float4*)p)[tid + i*256] = v[i];
    }
}

// ---------------- launch -----------------------------------------------------
extern "C" void kernel_launch(void* const* d_in, const int* in_sizes, int n_in,
                              void* d_out, int out_size)
{
    const float* x     = (const float*)d_in[0];
    const float* gamma = (const float*)d_in[1];
    const float* beta  = (const float*)d_in[2];
    const float* wq    = (const float*)d_in[3];
    const float* bq    = (const float*)d_in[4];
    const float* wk    = (const float*)d_in[5];
    const float* bk    = (const float*)d_in[6];
    const float* wv    = (const float*)d_in[7];
    const float* bv    = (const float*)d_in[8];
    const float* wo    = (const float*)d_in[9];
    const float* bo    = (const float*)d_in[10];
    float* out = (float*)d_out;

    float *xn, *q, *k, *v, *s, *ao;
    cudaGetSymbolAddress((void**)&xn, g_xn);
    cudaGetSymbolAddress((void**)&q,  g_q);
    cudaGetSymbolAddress((void**)&k,  g_k);
    cudaGetSymbolAddress((void**)&v,  g_v);
    cudaGetSymbolAddress((void**)&s,  g_s);
    cudaGetSymbolAddress((void**)&ao, g_ao);

    const float scale = 0.044194173824159216f;  // 512^-0.5

    // GroupNorm
    groupnorm_kernel<<<B_*G_, 256>>>(x, gamma, beta, xn);

    // Q,K,V projections: (16384x512) @ (512x512) + bias
    dim3 gproj(C_/128, MTOT/128, 1);
    sgemm_kernel<<<gproj, 256>>>(xn, wq, q, MTOT, C_, C_, 0, 0, 0, 0, 1.f, bq, nullptr);
    sgemm_kernel<<<gproj, 256>>>(xn, wk, k, MTOT, C_, C_, 0, 0, 0, 0, 1.f, bk, nullptr);
    sgemm_kernel<<<gproj, 256>>>(xn, wv, v, MTOT, C_, C_, 0, 0, 0, 0, 1.f, bv, nullptr);

    // scores = scale * Q K^T   per batch   (4096x4096, K=512)
    dim3 gsc(HW_/128, HW_/128, B_);
    sgemm_kernel<<<gsc, 256>>>(q, k, s, HW_, HW_, C_,
                               (long long)HW_*C_, (long long)HW_*C_,
                               (long long)HW_*HW_, 1, scale, nullptr, nullptr);

    // softmax rows
    softmax_kernel<<<B_*HW_, 256>>>(s);

    // attn_out = P @ V   per batch   (4096x512, K=4096)
    dim3 gav(C_/128, HW_/128, B_);
    sgemm_kernel<<<gav, 256>>>(s, v, ao, HW_, C_, HW_,
                               (long long)HW_*HW_, (long long)HW_*C_,
                               (long long)HW_*C_, 0, 1.f, nullptr, nullptr);

    // out = attn_out @ wo + bo + x
    sgemm_kernel<<<gproj, 256>>>(ao, wo, out, MTOT, C_, C_, 0, 0, 0, 0, 1.f, bo, x);
}

// round 6
// speedup vs baseline: 8.1183x; 8.1183x over previous
#include <cuda_runtime.h>
#include <cuda_bf16.h>
#include <math.h>

#define B_   4
#define HW_  4096          // 64*64
#define C_   512
#define G_   32
#define CG_  16
#define MTOT (B_*HW_)      // 16384

typedef __nv_bfloat16 bf16;

// ---------------- scratch (device globals; no allocations allowed) ----------
__device__ bf16  g_xn[(size_t)MTOT*C_];
__device__ bf16  g_q [(size_t)MTOT*C_];
__device__ bf16  g_k [(size_t)MTOT*C_];
__device__ bf16  g_v [(size_t)MTOT*C_];
__device__ bf16  g_vt[(size_t)B_*C_*HW_];        // V^T per batch [512][4096]
__device__ float g_s [(size_t)B_*HW_*HW_];       // fp32 scores 256 MiB
__device__ bf16  g_p [(size_t)B_*HW_*HW_];       // bf16 probs 128 MiB
__device__ bf16  g_ao[(size_t)MTOT*C_];
__device__ bf16  g_wT[(size_t)4*C_*C_];          // q,k,v,o transposed bf16

// ======================= helpers =============================================
__device__ __forceinline__ unsigned smem_u32(const void* p) {
    unsigned a;
    asm("{ .reg .u64 t; cvta.to.shared.u64 t, %1; cvt.u32.u64 %0, t; }"
        : "=r"(a) : "l"(p));
    return a;
}
__device__ __forceinline__ unsigned pack2(float a, float b) {
    __nv_bfloat162 t = __floats2bfloat162_rn(a, b);
    return *reinterpret_cast<unsigned*>(&t);
}

#define LDMX4(r, addr) \
    asm volatile("ldmatrix.sync.aligned.m8n8.x4.shared.b16 {%0,%1,%2,%3}, [%4];" \
        : "=r"((r)[0]), "=r"((r)[1]), "=r"((r)[2]), "=r"((r)[3]) : "r"(addr))

#define MMA16816(c, a, b0, b1) \
    asm volatile("mma.sync.aligned.m16n8k16.row.col.f32.bf16.bf16.f32 " \
        "{%0,%1,%2,%3}, {%4,%5,%6,%7}, {%8,%9}, {%0,%1,%2,%3};" \
        : "+f"((c)[0]), "+f"((c)[1]), "+f"((c)[2]), "+f"((c)[3]) \
        : "r"((a)[0]), "r"((a)[1]), "r"((a)[2]), "r"((a)[3]), "r"(b0), "r"(b1))

// ---------------- GroupNorm -> bf16 ----------------------------------------
__global__ __launch_bounds__(256) void groupnorm_kernel(
    const float* __restrict__ x, const float* __restrict__ gamma,
    const float* __restrict__ beta, bf16* __restrict__ xn)
{
    int bg = blockIdx.x;
    int b = bg / G_, g = bg % G_;
    const float* xp = x + (size_t)b * HW_ * C_ + g * CG_;
    bf16* op = xn + (size_t)b * HW_ * C_ + g * CG_;
    int tid = threadIdx.x;

    float s = 0.f, ss = 0.f;
    for (int p = tid; p < HW_; p += 256) {
        const float4* v4 = (const float4*)(xp + (size_t)p * C_);
        #pragma unroll
        for (int i = 0; i < 4; i++) {
            float4 t = v4[i];
            s  += t.x + t.y + t.z + t.w;
            ss += t.x*t.x + t.y*t.y + t.z*t.z + t.w*t.w;
        }
    }
    __shared__ float rs[256], rq[256];
    rs[tid] = s; rq[tid] = ss; __syncthreads();
    for (int o = 128; o > 0; o >>= 1) {
        if (tid < o) { rs[tid] += rs[tid+o]; rq[tid] += rq[tid+o]; }
        __syncthreads();
    }
    const float invn = 1.0f / (HW_ * CG_);
    float mean = rs[0] * invn;
    float var  = rq[0] * invn - mean * mean;
    float rstd = rsqrtf(var + 1e-6f);

    float gm[CG_], bt[CG_];
    #pragma unroll
    for (int i = 0; i < CG_; i++) {
        gm[i] = gamma[g*CG_ + i];
        bt[i] = beta [g*CG_ + i];
    }

    for (int p = tid; p < HW_; p += 256) {
        const float4* v4 = (const float4*)(xp + (size_t)p * C_);
        uint2* o2 = (uint2*)(op + (size_t)p * C_);
        #pragma unroll
        for (int i = 0; i < 4; i++) {
            float4 t = v4[i];
            float a0 = (t.x - mean) * rstd * gm[i*4+0] + bt[i*4+0];
            float a1 = (t.y - mean) * rstd * gm[i*4+1] + bt[i*4+1];
            float a2 = (t.z - mean) * rstd * gm[i*4+2] + bt[i*4+2];
            float a3 = (t.w - mean) * rstd * gm[i*4+3] + bt[i*4+3];
            uint2 u; u.x = pack2(a0, a1); u.y = pack2(a2, a3);
            o2[i] = u;
        }
    }
}

// ---------------- weight transpose+convert ----------------------------------
__global__ __launch_bounds__(256) void wtrans_kernel(
    const float* __restrict__ w0, const float* __restrict__ w1,
    const float* __restrict__ w2, const float* __restrict__ w3,
    bf16* __restrict__ out)
{
    int z = blockIdx.z;
    const float* w = (z == 0) ? w0 : (z == 1) ? w1 : (z == 2) ? w2 : w3;
    bf16* o = out + (size_t)z * C_ * C_;
    __shared__ float t[32][33];
    int c0 = blockIdx.x * 32, d0 = blockIdx.y * 32;
    int tx = threadIdx.x & 31, ty = threadIdx.x >> 5;
    #pragma unroll
    for (int i = 0; i < 32; i += 8)
        t[ty+i][tx] = w[(size_t)(c0+ty+i) * C_ + d0 + tx];
    __syncthreads();
    #pragma unroll
    for (int i = 0; i < 32; i += 8)
        o[(size_t)(d0+ty+i) * C_ + c0 + tx] = __float2bfloat16(t[tx][ty+i]);
}

// ---------------- V transpose (bf16) ----------------------------------------
__global__ __launch_bounds__(256) void vtrans_kernel(
    const bf16* __restrict__ v, bf16* __restrict__ vt)
{
    __shared__ bf16 t[32][34];
    int p0 = blockIdx.x * 32, c0 = blockIdx.y * 32, b = blockIdx.z;
    int tx = threadIdx.x & 31, ty = threadIdx.x >> 5;
    #pragma unroll
    for (int i = 0; i < 32; i += 8)
        t[ty+i][tx] = v[((size_t)b * HW_ + p0+ty+i) * C_ + c0 + tx];
    __syncthreads();
    #pragma unroll
    for (int i = 0; i < 32; i += 8)
        vt[((size_t)b * C_ + c0+ty+i) * HW_ + p0 + tx] = t[tx][ty+i];
}

// ---------------- HMMA bf16 GEMM: C = alpha*A@B^T (+bias)(+resid) -----------
// A: [M,K] bf16 row-major. B: [N,K] bf16 row-major. Output fp32 (Cf) or bf16
// (Cb), row-major MxN. blockIdx.z batches by strides.
// Block tile 128x128x64, 8 warps (2x4), warp tile 64x32, 2-stage cp.async.
#define KT 64
#define STAGE_BYTES 32768   // A tile 16KB + B tile 16KB

__device__ __forceinline__ void load_tile_pair(
    unsigned stage_base, const bf16* __restrict__ A, const bf16* __restrict__ B,
    int lda, int ldb, int brow, int bcol, int k0, int tid)
{
    #pragma unroll
    for (int i = 0; i < 4; i++) {
        int id  = i * 256 + tid;
        int row = id >> 3, cg = id & 7;
        const bf16* ga = A + (long long)(brow + row) * lda + k0 + cg * 8;
        unsigned sa = stage_base + row * 128 + ((cg ^ (row & 7)) << 4);
        asm volatile("cp.async.cg.shared.global [%0], [%1], 16;" :: "r"(sa), "l"(ga));
        const bf16* gb = B + (long long)(bcol + row) * ldb + k0 + cg * 8;
        unsigned sbm = stage_base + 16384 + row * 128 + ((cg ^ (row & 7)) << 4);
        asm volatile("cp.async.cg.shared.global [%0], [%1], 16;" :: "r"(sbm), "l"(gb));
    }
}

__global__ void __launch_bounds__(256, 2) gemm_bf16(
    const bf16* __restrict__ A, const bf16* __restrict__ B,
    int M, int N, int K,
    long long sA, long long sB, long long sC,
    float alpha,
    const float* __restrict__ bias,
    const float* __restrict__ resid,
    float* __restrict__ Cf, bf16* __restrict__ Cb)
{
    extern __shared__ char smem[];
    const unsigned s0 = smem_u32(smem);
    const int tid = threadIdx.x, wid = tid >> 5, lane = tid & 31;
    const int warp_m = wid & 1, warp_n = wid >> 1;    // 2 x 4 warp grid

    A += (long long)blockIdx.z * sA;
    B += (long long)blockIdx.z * sB;
    const long long cb0 = (long long)blockIdx.z * sC;
    const int brow = blockIdx.y * 128, bcol = blockIdx.x * 128;

    // ldmatrix per-thread address components
    const int g  = lane >> 3, li = lane & 7;
    const int rowA = (g & 1) * 8 + li;   // within m16 tile
    const int kselA = g >> 1;            // 16B k-group select
    const int rowB = (g >> 1) * 8 + li;  // within n16 (2 n-tiles)
    const int kselB = g & 1;

    float acc[4][4][4];
    #pragma unroll
    for (int mt = 0; mt < 4; mt++)
        #pragma unroll
        for (int nt = 0; nt < 4; nt++)
            #pragma unroll
            for (int e = 0; e < 4; e++) acc[mt][nt][e] = 0.f;

    const int nt_tiles = K / KT;

    load_tile_pair(s0, A, B, K, K, brow, bcol, 0, tid);
    asm volatile("cp.async.commit_group;");

    for (int t = 0; t < nt_tiles; t++) {
        if (t + 1 < nt_tiles) {
            load_tile_pair(s0 + ((t + 1) & 1) * STAGE_BYTES, A, B, K, K,
                           brow, bcol, (t + 1) * KT, tid);
            asm volatile("cp.async.commit_group;");
            asm volatile("cp.async.wait_group 1;");
        } else {
            asm volatile("cp.async.wait_group 0;");
        }
        __syncthreads();

        const unsigned aBase = s0 + (t & 1) * STAGE_BYTES;
        const unsigned bBase = aBase + 16384;
        #pragma unroll
        for (int kk = 0; kk < 4; kk++) {
            unsigned af[4][4];
            #pragma unroll
            for (int mt = 0; mt < 4; mt++) {
                int r = warp_m * 64 + mt * 16 + rowA;
                unsigned addr = aBase + r * 128 + (((kk * 2 + kselA) ^ li) << 4);
                LDMX4(af[mt], addr);
            }
            unsigned bfx[2][4];
            #pragma unroll
            for (int nh = 0; nh < 2; nh++) {
                int r = warp_n * 32 + nh * 16 + rowB;
                unsigned addr = bBase + r * 128 + (((kk * 2 + kselB) ^ li) << 4);
                LDMX4(bfx[nh], addr);
            }
            #pragma unroll
            for (int mt = 0; mt < 4; mt++) {
                #pragma unroll
                for (int nt = 0; nt < 4; nt++) {
                    unsigned b0 = bfx[nt >> 1][(nt & 1) * 2];
                    unsigned b1 = bfx[nt >> 1][(nt & 1) * 2 + 1];
                    MMA16816(acc[mt][nt], af[mt], b0, b1);
                }
            }
        }
        __syncthreads();
    }

    // epilogue: acc layout c0,c1 -> (row, col..col+1); c2,c3 -> (row+8, ...)
    const int er = lane >> 2, ec = (lane & 3) * 2;
    #pragma unroll
    for (int mt = 0; mt < 4; mt++) {
        #pragma unroll
        for (int half = 0; half < 2; half++) {
            long long grow = brow + warp_m * 64 + mt * 16 + er + half * 8;
            #pragma unroll
            for (int nt = 0; nt < 4; nt++) {
                int col = bcol + warp_n * 32 + nt * 8 + ec;
                float v0 = acc[mt][nt][half * 2]     * alpha;
                float v1 = acc[mt][nt][half * 2 + 1] * alpha;
                if (bias) { v0 += bias[col]; v1 += bias[col + 1]; }
                long long base = cb0 + grow * (long long)N + col;
                if (resid) {
                    float2 r = *(const float2*)(resid + base);
                    v0 += r.x; v1 += r.y;
                }
                if (Cf) {
                    float2 o = {v0, v1};
                    *(float2*)(Cf + base) = o;
                } else {
                    *(unsigned*)(Cb + base) = pack2(v0, v1);
                }
            }
        }
    }
}

// ---------------- row softmax fp32 -> bf16 ----------------------------------
__global__ __launch_bounds__(256) void softmax_kernel(
    const float* __restrict__ S, bf16* __restrict__ P)
{
    __shared__ float red[256];
    const float* p = S + (long long)blockIdx.x * HW_;
    bf16* o = P + (long long)blockIdx.x * HW_;
    int tid = threadIdx.x;

    float4 v[4];
    float mx = -1e30f;
    #pragma unroll
    for (int i = 0; i < 4; i++) {
        v[i] = ((const float4*)p)[tid + i*256];
        mx = fmaxf(mx, fmaxf(fmaxf(v[i].x, v[i].y), fmaxf(v[i].z, v[i].w)));
    }
    red[tid] = mx; __syncthreads();
    for (int off = 128; off > 0; off >>= 1) {
        if (tid < off) red[tid] = fmaxf(red[tid], red[tid+off]);
        __syncthreads();
    }
    mx = red[0]; __syncthreads();

    float sum = 0.f;
    #pragma unroll
    for (int i = 0; i < 4; i++) {
        v[i].x = __expf(v[i].x - mx);
        v[i].y = __expf(v[i].y - mx);
        v[i].z = __expf(v[i].z - mx);
        v[i].w = __expf(v[i].w - mx);
        sum += v[i].x + v[i].y + v[i].z + v[i].w;
    }
    red[tid] = sum; __syncthreads();
    for (int off = 128; off > 0; off >>= 1) {
        if (tid < off) red[tid] += red[tid+off];
        __syncthreads();
    }
    float inv = 1.0f / red[0];
    #pragma unroll
    for (int i = 0; i < 4; i++) {
        uint2 u;
        u.x = pack2(v[i].x * inv, v[i].y * inv);
        u.y = pack2(v[i].z * inv, v[i].w * inv);
        ((uint2*)o)[tid + i*256] = u;
    }
}

// ---------------- launch -----------------------------------------------------
extern "C" void kernel_launch(void* const* d_in, const int* in_sizes, int n_in,
                              void* d_out, int out_size)
{
    const float* x     = (const float*)d_in[0];
    const float* gamma = (const float*)d_in[1];
    const float* beta  = (const float*)d_in[2];
    const float* wq    = (const float*)d_in[3];
    const float* bq    = (const float*)d_in[4];
    const float* wk    = (const float*)d_in[5];
    const float* bk    = (const float*)d_in[6];
    const float* wv    = (const float*)d_in[7];
    const float* bv    = (const float*)d_in[8];
    const float* wo    = (const float*)d_in[9];
    const float* bo    = (const float*)d_in[10];
    float* out = (float*)d_out;

    bf16 *xn, *q, *k, *v, *vt, *p, *ao, *wT;
    float *s;
    cudaGetSymbolAddress((void**)&xn, g_xn);
    cudaGetSymbolAddress((void**)&q,  g_q);
    cudaGetSymbolAddress((void**)&k,  g_k);
    cudaGetSymbolAddress((void**)&v,  g_v);
    cudaGetSymbolAddress((void**)&vt, g_vt);
    cudaGetSymbolAddress((void**)&s,  g_s);
    cudaGetSymbolAddress((void**)&p,  g_p);
    cudaGetSymbolAddress((void**)&ao, g_ao);
    cudaGetSymbolAddress((void**)&wT, g_wT);

    const int SMEM_DYN = 2 * STAGE_BYTES;   // 64 KB
    cudaFuncSetAttribute(gemm_bf16, cudaFuncAttributeMaxDynamicSharedMemorySize,
                         SMEM_DYN);

    const float scale = 0.044194173824159216f;   // 512^-0.5

    // GroupNorm -> bf16
    groupnorm_kernel<<<B_ * G_, 256>>>(x, gamma, beta, xn);

    // transpose + convert weights
    wtrans_kernel<<<dim3(C_/32, C_/32, 4), 256>>>(wq, wk, wv, wo, wT);

    // Q,K,V projections: (16384x512) @ wT^T + bias -> bf16
    dim3 gproj(C_/128, MTOT/128, 1);
    gemm_bf16<<<gproj, 256, SMEM_DYN>>>(xn, wT + 0*(size_t)C_*C_, MTOT, C_, C_,
                                        0, 0, 0, 1.f, bq, nullptr, nullptr, q);
    gemm_bf16<<<gproj, 256, SMEM_DYN>>>(xn, wT + 1*(size_t)C_*C_, MTOT, C_, C_,
                                        0, 0, 0, 1.f, bk, nullptr, nullptr, k);
    gemm_bf16<<<gproj, 256, SMEM_DYN>>>(xn, wT + 2*(size_t)C_*C_, MTOT, C_, C_,
                                        0, 0, 0, 1.f, bv, nullptr, nullptr, v);

    // V transpose per batch
    vtrans_kernel<<<dim3(HW_/32, C_/32, B_), 256>>>(v, vt);

    // scores = scale * Q K^T  -> fp32
    dim3 gsc(HW_/128, HW_/128, B_);
    gemm_bf16<<<gsc, 256, SMEM_DYN>>>(q, k, HW_, HW_, C_,
                                      (long long)HW_*C_, (long long)HW_*C_,
                                      (long long)HW_*HW_, scale,
                                      nullptr, nullptr, s, nullptr);

    // softmax rows -> bf16 P
    softmax_kernel<<<B_ * HW_, 256>>>(s, p);

    // attn_out = P @ V = P @ (V^T)^T  -> bf16
    dim3 gav(C_/128, HW_/128, B_);
    gemm_bf16<<<gav, 256, SMEM_DYN>>>(p, vt, HW_, C_, HW_,
                                      (long long)HW_*HW_, (long long)C_*HW_,
                                      (long long)HW_*C_, 1.f,
                                      nullptr, nullptr, nullptr, ao);

    // out = attn_out @ wo + bo + x  -> fp32
    gemm_bf16<<<gproj, 256, SMEM_DYN>>>(ao, wT + 3*(size_t)C_*C_, MTOT, C_, C_,
                                        0, 0, 0, 1.f, bo, x, out, nullptr);
}

// round 7
// speedup vs baseline: 8.1701x; 1.0064x over previous
#include <cuda_runtime.h>
#include <cuda_bf16.h>
#include <math.h>

#define B_   4
#define HW_  4096          // 64*64
#define C_   512
#define G_   32
#define CG_  16
#define MTOT (B_*HW_)      // 16384

typedef __nv_bfloat16 bf16;

// ---------------- scratch (device globals; no allocations allowed) ----------
__device__ bf16  g_xn[(size_t)MTOT*C_];
__device__ bf16  g_q [(size_t)MTOT*C_];
__device__ bf16  g_k [(size_t)MTOT*C_];
__device__ bf16  g_vt[(size_t)B_*C_*HW_];        // V^T per batch [512][4096]
__device__ bf16  g_s [(size_t)B_*HW_*HW_];       // bf16 scores/probs 128 MiB
__device__ bf16  g_ao[(size_t)MTOT*C_];
__device__ bf16  g_wT[(size_t)4*C_*C_];          // q,k,v,o transposed bf16

// ======================= helpers =============================================
__device__ __forceinline__ unsigned smem_u32(const void* p) {
    unsigned a;
    asm("{ .reg .u64 t; cvta.to.shared.u64 t, %1; cvt.u32.u64 %0, t; }"
        : "=r"(a) : "l"(p));
    return a;
}
__device__ __forceinline__ unsigned pack2(float a, float b) {
    __nv_bfloat162 t = __floats2bfloat162_rn(a, b);
    return *reinterpret_cast<unsigned*>(&t);
}

#define LDMX4(r, addr) \
    asm volatile("ldmatrix.sync.aligned.m8n8.x4.shared.b16 {%0,%1,%2,%3}, [%4];" \
        : "=r"((r)[0]), "=r"((r)[1]), "=r"((r)[2]), "=r"((r)[3]) : "r"(addr))

#define MMA16816(c, a, b0, b1) \
    asm volatile("mma.sync.aligned.m16n8k16.row.col.f32.bf16.bf16.f32 " \
        "{%0,%1,%2,%3}, {%4,%5,%6,%7}, {%8,%9}, {%0,%1,%2,%3};" \
        : "+f"((c)[0]), "+f"((c)[1]), "+f"((c)[2]), "+f"((c)[3]) \
        : "r"((a)[0]), "r"((a)[1]), "r"((a)[2]), "r"((a)[3]), "r"(b0), "r"(b1))

// ---------------- GroupNorm -> bf16 ----------------------------------------
__global__ __launch_bounds__(256) void groupnorm_kernel(
    const float* __restrict__ x, const float* __restrict__ gamma,
    const float* __restrict__ beta, bf16* __restrict__ xn)
{
    int bg = blockIdx.x;
    int b = bg / G_, g = bg % G_;
    const float* xp = x + (size_t)b * HW_ * C_ + g * CG_;
    bf16* op = xn + (size_t)b * HW_ * C_ + g * CG_;
    int tid = threadIdx.x;

    float s = 0.f, ss = 0.f;
    for (int p = tid; p < HW_; p += 256) {
        const float4* v4 = (const float4*)(xp + (size_t)p * C_);
        #pragma unroll
        for (int i = 0; i < 4; i++) {
            float4 t = v4[i];
            s  += t.x + t.y + t.z + t.w;
            ss += t.x*t.x + t.y*t.y + t.z*t.z + t.w*t.w;
        }
    }
    __shared__ float rs[256], rq[256];
    rs[tid] = s; rq[tid] = ss; __syncthreads();
    for (int o = 128; o > 0; o >>= 1) {
        if (tid < o) { rs[tid] += rs[tid+o]; rq[tid] += rq[tid+o]; }
        __syncthreads();
    }
    const float invn = 1.0f / (HW_ * CG_);
    float mean = rs[0] * invn;
    float var  = rq[0] * invn - mean * mean;
    float rstd = rsqrtf(var + 1e-6f);

    float gm[CG_], bt[CG_];
    #pragma unroll
    for (int i = 0; i < CG_; i++) {
        gm[i] = gamma[g*CG_ + i];
        bt[i] = beta [g*CG_ + i];
    }

    for (int p = tid; p < HW_; p += 256) {
        const float4* v4 = (const float4*)(xp + (size_t)p * C_);
        uint2* o2 = (uint2*)(op + (size_t)p * C_);
        #pragma unroll
        for (int i = 0; i < 4; i++) {
            float4 t = v4[i];
            float a0 = (t.x - mean) * rstd * gm[i*4+0] + bt[i*4+0];
            float a1 = (t.y - mean) * rstd * gm[i*4+1] + bt[i*4+1];
            float a2 = (t.z - mean) * rstd * gm[i*4+2] + bt[i*4+2];
            float a3 = (t.w - mean) * rstd * gm[i*4+3] + bt[i*4+3];
            uint2 u; u.x = pack2(a0, a1); u.y = pack2(a2, a3);
            o2[i] = u;
        }
    }
}

// ---------------- weight transpose+convert ----------------------------------
__global__ __launch_bounds__(256) void wtrans_kernel(
    const float* __restrict__ w0, const float* __restrict__ w1,
    const float* __restrict__ w2, const float* __restrict__ w3,
    bf16* __restrict__ out)
{
    int z = blockIdx.z;
    const float* w = (z == 0) ? w0 : (z == 1) ? w1 : (z == 2) ? w2 : w3;
    bf16* o = out + (size_t)z * C_ * C_;
    __shared__ float t[32][33];
    int c0 = blockIdx.x * 32, d0 = blockIdx.y * 32;
    int tx = threadIdx.x & 31, ty = threadIdx.x >> 5;
    #pragma unroll
    for (int i = 0; i < 32; i += 8)
        t[ty+i][tx] = w[(size_t)(c0+ty+i) * C_ + d0 + tx];
    __syncthreads();
    #pragma unroll
    for (int i = 0; i < 32; i += 8)
        o[(size_t)(d0+ty+i) * C_ + c0 + tx] = __float2bfloat16(t[tx][ty+i]);
}

// ---------------- HMMA bf16 GEMM: C = alpha*A@B^T (+cbias)(+rbias)(+resid) --
// A: [M,K] bf16 row-major. B: [N,K] bf16 row-major. Out fp32 (Cf) or bf16 (Cb).
// Block tile 128x256x64, 8 warps (2x4), warp tile 64x64, 4-stage cp.async.
#define KT 64
#define STAGE_BYTES 49152   // A tile 16KB + B tile 32KB
#define NSTAGE 4

__device__ __forceinline__ void load_stage(
    unsigned base, const bf16* __restrict__ A, const bf16* __restrict__ B,
    int K, int brow, int bcol, int k0, int tid)
{
    #pragma unroll
    for (int i = 0; i < 4; i++) {
        int id = i * 256 + tid;
        int row = id >> 3, cg = id & 7;
        const bf16* g = A + (long long)(brow + row) * K + k0 + cg * 8;
        unsigned s = base + row * 128 + ((cg ^ (row & 7)) << 4);
        asm volatile("cp.async.cg.shared.global [%0], [%1], 16;" :: "r"(s), "l"(g));
    }
    #pragma unroll
    for (int i = 0; i < 8; i++) {
        int id = i * 256 + tid;
        int row = id >> 3, cg = id & 7;
        const bf16* g = B + (long long)(bcol + row) * K + k0 + cg * 8;
        unsigned s = base + 16384 + row * 128 + ((cg ^ (row & 7)) << 4);
        asm volatile("cp.async.cg.shared.global [%0], [%1], 16;" :: "r"(s), "l"(g));
    }
}

__global__ void __launch_bounds__(256, 1) gemm_bf16(
    const bf16* __restrict__ A, const bf16* __restrict__ B,
    int M, int N, int K,
    long long sA, long long sB, long long sC,
    float alpha,
    const float* __restrict__ cbias,
    const float* __restrict__ rbias,
    const float* __restrict__ resid,
    float* __restrict__ Cf, bf16* __restrict__ Cb)
{
    extern __shared__ char smem[];
    const unsigned s0 = smem_u32(smem);
    const int tid = threadIdx.x, wid = tid >> 5, lane = tid & 31;
    const int warp_m = wid & 1, warp_n = wid >> 1;    // 2 x 4 warp grid

    A += (long long)blockIdx.z * sA;
    B += (long long)blockIdx.z * sB;
    const long long cb0 = (long long)blockIdx.z * sC;
    const int brow = blockIdx.y * 128, bcol = blockIdx.x * 256;

    // ldmatrix per-thread address components
    const int g  = lane >> 3, li = lane & 7;
    const int rowA = (g & 1) * 8 + li;   // within m16 tile
    const int kselA = g >> 1;            // 16B k-group select
    const int rowB = (g >> 1) * 8 + li;  // within n16
    const int kselB = g & 1;

    float acc[4][8][4];
    #pragma unroll
    for (int mt = 0; mt < 4; mt++)
        #pragma unroll
        for (int nt = 0; nt < 8; nt++)
            #pragma unroll
            for (int e = 0; e < 4; e++) acc[mt][nt][e] = 0.f;

    const int nc = K / KT;

    #pragma unroll
    for (int t = 0; t < NSTAGE - 1; t++) {
        load_stage(s0 + t * STAGE_BYTES, A, B, K, brow, bcol, t * KT, tid);
        asm volatile("cp.async.commit_group;");
    }

    for (int t = 0; t < nc; t++) {
        if (t < nc - 2)      asm volatile("cp.async.wait_group 2;");
        else if (t == nc - 2) asm volatile("cp.async.wait_group 1;");
        else                  asm volatile("cp.async.wait_group 0;");
        __syncthreads();

        if (t + NSTAGE - 1 < nc) {
            load_stage(s0 + ((t + NSTAGE - 1) & 3) * STAGE_BYTES, A, B, K,
                       brow, bcol, (t + NSTAGE - 1) * KT, tid);
            asm volatile("cp.async.commit_group;");
        }

        const unsigned aBase = s0 + (t & 3) * STAGE_BYTES;
        const unsigned bBase = aBase + 16384;
        #pragma unroll
        for (int kk = 0; kk < 4; kk++) {
            unsigned af[4][4];
            #pragma unroll
            for (int mt = 0; mt < 4; mt++) {
                int r = warp_m * 64 + mt * 16 + rowA;
                unsigned addr = aBase + r * 128 + (((kk * 2 + kselA) ^ li) << 4);
                LDMX4(af[mt], addr);
            }
            unsigned bfx[4][4];
            #pragma unroll
            for (int nh = 0; nh < 4; nh++) {
                int r = warp_n * 64 + nh * 16 + rowB;
                unsigned addr = bBase + r * 128 + (((kk * 2 + kselB) ^ li) << 4);
                LDMX4(bfx[nh], addr);
            }
            #pragma unroll
            for (int mt = 0; mt < 4; mt++) {
                #pragma unroll
                for (int nt = 0; nt < 8; nt++) {
                    unsigned b0 = bfx[nt >> 1][(nt & 1) * 2];
                    unsigned b1 = bfx[nt >> 1][(nt & 1) * 2 + 1];
                    MMA16816(acc[mt][nt], af[mt], b0, b1);
                }
            }
        }
    }

    // epilogue
    const int er = lane >> 2, ec = (lane & 3) * 2;
    #pragma unroll
    for (int mt = 0; mt < 4; mt++) {
        #pragma unroll
        for (int half = 0; half < 2; half++) {
            long long grow = brow + warp_m * 64 + mt * 16 + er + half * 8;
            float rb = rbias ? rbias[grow] : 0.f;
            #pragma unroll
            for (int nt = 0; nt < 8; nt++) {
                int col = bcol + warp_n * 64 + nt * 8 + ec;
                float v0 = acc[mt][nt][half * 2]     * alpha + rb;
                float v1 = acc[mt][nt][half * 2 + 1] * alpha + rb;
                if (cbias) { v0 += cbias[col]; v1 += cbias[col + 1]; }
                long long base = cb0 + grow * (long long)N + col;
                if (resid) {
                    float2 r = *(const float2*)(resid + base);
                    v0 += r.x; v1 += r.y;
                }
                if (Cf) {
                    float2 o = {v0, v1};
                    *(float2*)(Cf + base) = o;
                } else {
                    *(unsigned*)(Cb + base) = pack2(v0, v1);
                }
            }
        }
    }
}

// ---------------- row softmax bf16 in-place ----------------------------------
__global__ __launch_bounds__(256) void softmax_kernel(bf16* __restrict__ S)
{
    __shared__ float red[256];
    bf16* p = S + (long long)blockIdx.x * HW_;
    int tid = threadIdx.x;

    uint4 u[2];
    u[0] = ((const uint4*)p)[tid];
    u[1] = ((const uint4*)p)[tid + 256];
    float f[16];
    #pragma unroll
    for (int i = 0; i < 2; i++) {
        const unsigned* w = (const unsigned*)&u[i];
        #pragma unroll
        for (int j = 0; j < 4; j++) {
            float2 d = __bfloat1622float2(*(const __nv_bfloat162*)&w[j]);
            f[i*8 + j*2]     = d.x;
            f[i*8 + j*2 + 1] = d.y;
        }
    }
    float mx = -1e30f;
    #pragma unroll
    for (int i = 0; i < 16; i++) mx = fmaxf(mx, f[i]);
    red[tid] = mx; __syncthreads();
    for (int o = 128; o > 0; o >>= 1) {
        if (tid < o) red[tid] = fmaxf(red[tid], red[tid+o]);
        __syncthreads();
    }
    mx = red[0]; __syncthreads();

    float sum = 0.f;
    #pragma unroll
    for (int i = 0; i < 16; i++) { f[i] = __expf(f[i] - mx); sum += f[i]; }
    red[tid] = sum; __syncthreads();
    for (int o = 128; o > 0; o >>= 1) {
        if (tid < o) red[tid] += red[tid+o];
        __syncthreads();
    }
    float inv = 1.0f / red[0];

    #pragma unroll
    for (int i = 0; i < 2; i++) {
        unsigned* w = (unsigned*)&u[i];
        #pragma unroll
        for (int j = 0; j < 4; j++)
            w[j] = pack2(f[i*8 + j*2] * inv, f[i*8 + j*2 + 1] * inv);
    }
    ((uint4*)p)[tid]       = u[0];
    ((uint4*)p)[tid + 256] = u[1];
}

// ---------------- launch -----------------------------------------------------
extern "C" void kernel_launch(void* const* d_in, const int* in_sizes, int n_in,
                              void* d_out, int out_size)
{
    const float* x     = (const float*)d_in[0];
    const float* gamma = (const float*)d_in[1];
    const float* beta  = (const float*)d_in[2];
    const float* wq    = (const float*)d_in[3];
    const float* bq    = (const float*)d_in[4];
    const float* wk    = (const float*)d_in[5];
    const float* bk    = (const float*)d_in[6];
    const float* wv    = (const float*)d_in[7];
    const float* bv    = (const float*)d_in[8];
    const float* wo    = (const float*)d_in[9];
    const float* bo    = (const float*)d_in[10];
    float* out = (float*)d_out;

    bf16 *xn, *q, *k, *vt, *s, *ao, *wT;
    cudaGetSymbolAddress((void**)&xn, g_xn);
    cudaGetSymbolAddress((void**)&q,  g_q);
    cudaGetSymbolAddress((void**)&k,  g_k);
    cudaGetSymbolAddress((void**)&vt, g_vt);
    cudaGetSymbolAddress((void**)&s,  g_s);
    cudaGetSymbolAddress((void**)&ao, g_ao);
    cudaGetSymbolAddress((void**)&wT, g_wT);

    const int SMEM_DYN = NSTAGE * STAGE_BYTES;   // 192 KB
    cudaFuncSetAttribute(gemm_bf16, cudaFuncAttributeMaxDynamicSharedMemorySize,
                         SMEM_DYN);

    const float scale = 0.044194173824159216f;   // 512^-0.5

    // GroupNorm -> bf16
    groupnorm_kernel<<<B_ * G_, 256>>>(x, gamma, beta, xn);

    // transpose + convert weights
    wtrans_kernel<<<dim3(C_/32, C_/32, 4), 256>>>(wq, wk, wv, wo, wT);

    // Q,K projections: (16384x512) @ wT^T + bias -> bf16
    dim3 gproj(C_/256, MTOT/128, 1);
    gemm_bf16<<<gproj, 256, SMEM_DYN>>>(xn, wT + 0*(size_t)C_*C_, MTOT, C_, C_,
                                        0, 0, 0, 1.f, bq, nullptr, nullptr,
                                        nullptr, q);
    gemm_bf16<<<gproj, 256, SMEM_DYN>>>(xn, wT + 1*(size_t)C_*C_, MTOT, C_, C_,
                                        0, 0, 0, 1.f, bk, nullptr, nullptr,
                                        nullptr, k);

    // V^T directly: vt_b = wT_v @ xn_b^T + bv(row)   [512 x 4096] per batch
    dim3 gvt(HW_/256, C_/128, B_);
    gemm_bf16<<<gvt, 256, SMEM_DYN>>>(wT + 2*(size_t)C_*C_, xn, C_, HW_, C_,
                                      0, (long long)HW_*C_, (long long)C_*HW_,
                                      1.f, nullptr, bv, nullptr, nullptr, vt);

    // scores = scale * Q K^T -> bf16
    dim3 gsc(HW_/256, HW_/128, B_);
    gemm_bf16<<<gsc, 256, SMEM_DYN>>>(q, k, HW_, HW_, C_,
                                      (long long)HW_*C_, (long long)HW_*C_,
                                      (long long)HW_*HW_, scale,
                                      nullptr, nullptr, nullptr, nullptr, s);

    // softmax rows in-place (bf16)
    softmax_kernel<<<B_ * HW_, 256>>>(s);

    // attn_out = P @ (V^T)^T -> bf16
    dim3 gav(C_/256, HW_/128, B_);
    gemm_bf16<<<gav, 256, SMEM_DYN>>>(s, vt, HW_, C_, HW_,
                                      (long long)HW_*HW_, (long long)C_*HW_,
                                      (long long)HW_*C_, 1.f,
                                      nullptr, nullptr, nullptr, nullptr, ao);

    // out = attn_out @ wo + bo + x -> fp32
    gemm_bf16<<<gproj, 256, SMEM_DYN>>>(ao, wT + 3*(size_t)C_*C_, MTOT, C_, C_,
                                        0, 0, 0, 1.f, bo, nullptr, x, out, nullptr);
}